// round 9
// baseline (speedup 1.0000x reference)
#include <cuda_runtime.h>
#include <cuda_bf16.h>
#include <float.h>

#define BATCH 256
#define NQ 1000
#define NC 80
#define TOPK 300
#define THRESH 0.05f

#define RPB 128            // rows per producer tile
#define PAD 21             // padded float4 per row
#define NTILES 2000        // 256000 / 128
#define NSORT 256          // sorter blocks (one per batch)
#define NPRODB 336         // persistent producer blocks
#define GRID (NSORT + NPRODB)   // 592 = single wave at 4 blocks/SM

typedef unsigned long long u64;
typedef unsigned int u32;

__device__ u64 g_keys[BATCH * NQ];
__device__ int g_done[BATCH];          // zero-init; each sorter resets its slot

// Order-preserving bijection float -> uint32 (monotone increasing)
__device__ __forceinline__ u32 fkey(float f) {
    u32 u = __float_as_uint(f);
    int  fl = ((int)u) >> 31;
    return u ^ ((u32)fl | 0x80000000u);
}
__device__ __forceinline__ float ikey(u32 k) {
    u32 u = (k & 0x80000000u) ? (k ^ 0x80000000u) : ~k;
    return __uint_as_float(u);
}

// ---------------------------------------------------------------------------
// Producer tile: stage 128 rows (43KB, rows padded to 21 float4), 4 thr/row
// scan 5 float4 (ascending class order = jax argmax tie-break), 2-stage shfl
// pair reduce. key = [fkey(masked):32 | (1023-qi):10 | label:7].
// Doorbell: __threadfence + atomicAdd(done[batch], rows).
// ---------------------------------------------------------------------------
__device__ __forceinline__ void do_tile(int m, float4* sm,
                                        const float* __restrict__ logits) {
    const float4* in = reinterpret_cast<const float4*>(logits) + (size_t)m * (RPB * 20);
    int t = threadIdx.x;

    #pragma unroll
    for (int u = 0; u < 5; u++) {               // 512*5 = 2560 float4, coalesced
        int g = u * 512 + t;
        int row = g / 20;
        int col = g - row * 20;
        sm[row * PAD + col] = in[g];
    }
    __syncthreads();

    int r = t >> 2, q = t & 3;                  // 4 threads per row
    const float4* rp = &sm[r * PAD + q * 5];

    float v = -FLT_MAX; int c = 0;
    #pragma unroll
    for (int k = 0; k < 5; k++) {
        float4 x = rp[k];
        int base = q * 20 + k * 4;
        if (x.x > v) { v = x.x; c = base;     }
        if (x.y > v) { v = x.y; c = base + 1; }
        if (x.z > v) { v = x.z; c = base + 2; }
        if (x.w > v) { v = x.w; c = base + 3; }
    }
    #pragma unroll
    for (int off = 1; off <= 2; off <<= 1) {
        float v2 = __shfl_xor_sync(0xffffffffu, v, off);
        int   c2 = __shfl_xor_sync(0xffffffffu, c, off);
        if (v2 > v || (v2 == v && c2 < c)) { v = v2; c = c2; }
    }
    if (q == 0) {
        float s = 1.0f / (1.0f + expf(-v));
        float masked = (s > THRESH) ? s : -1.0f;
        int gq = m * RPB + r;
        int qi = gq % NQ;
        g_keys[gq] = ((u64)fkey(masked) << 17)
                   | ((u64)(1023 - qi) << 7)
                   | (u32)c;
    }
    __syncthreads();                             // all key writes done
    if (t == 0) {
        __threadfence();                         // keys coherent before doorbell
        int r0 = m * RPB;
        int b0 = r0 / NQ;
        int off = r0 - b0 * NQ;
        int n0 = min(NQ - off, RPB);
        atomicAdd(&g_done[b0], n0);
        if (n0 < RPB) atomicAdd(&g_done[b0 + 1], RPB - n0);
    }
}

// ---------------------------------------------------------------------------
// Sorter: proven unrolled bitonic — 512 threads, 2 keys/thread,
// 40 shfl phases, 5 register phases, 10 smem phases (1 barrier each).
// ---------------------------------------------------------------------------
__device__ __forceinline__ u64 shfl_xor_u64(u64 v, int m) {
    u32 lo = __shfl_xor_sync(0xffffffffu, (u32)v, m);
    u32 hi = __shfl_xor_sync(0xffffffffu, (u32)(v >> 32), m);
    return ((u64)hi << 32) | lo;
}

template<int K, int J>
__device__ __forceinline__ void phase_shfl(u64 v[2], int lane, int warp) {
    #pragma unroll
    for (int r = 0; r < 2; r++) {
        int i = (warp << 6) | (r << 5) | lane;
        u64 o = shfl_xor_u64(v[r], J);
        bool keep_hi = ((i & K) == 0) != ((lane & J) != 0);
        bool ogt = o > v[r];
        v[r] = (keep_hi == ogt) ? o : v[r];
    }
}

template<int K>
__device__ __forceinline__ void phase_reg32(u64 v[2], int warp) {
    bool desc = ((warp << 6) & K) == 0;
    u64 a = v[0], b = v[1];
    bool agt = a > b;
    u64 mx = agt ? a : b;
    u64 mn = agt ? b : a;
    v[0] = desc ? mx : mn;
    v[1] = desc ? mn : mx;
}

template<int K, int J, int BUF>
__device__ __forceinline__ void phase_smem(u64 v[2], u64 (*sm)[1024], int i0) {
    sm[BUF][i0]      = v[0];
    sm[BUF][i0 + 32] = v[1];
    __syncthreads();
    #pragma unroll
    for (int r = 0; r < 2; r++) {
        int i = i0 + (r << 5);
        u64 o = sm[BUF][i ^ J];
        bool keep_hi = ((i & K) == 0) != ((i & J) != 0);
        bool ogt = o > v[r];
        v[r] = (keep_hi == ogt) ? o : v[r];
    }
}

template<int K>
__device__ __forceinline__ void phases_shfl_16_1(u64 v[2], int lane, int warp) {
    phase_shfl<K, 16>(v, lane, warp);
    phase_shfl<K,  8>(v, lane, warp);
    phase_shfl<K,  4>(v, lane, warp);
    phase_shfl<K,  2>(v, lane, warp);
    phase_shfl<K,  1>(v, lane, warp);
}

__device__ __forceinline__ void do_topk(int b, u64 (*sm)[1024],
                                        const float* __restrict__ boxes,
                                        const float* __restrict__ tsizes,
                                        float* __restrict__ out) {
    int t = threadIdx.x;
    int warp = t >> 5, lane = t & 31;
    int i0 = (warp << 6) | lane;

    // Wait for this batch's 1000 keys
    if (t == 0) {
        volatile int* vd = g_done;
        while (vd[b] < NQ) __nanosleep(128);
        __threadfence();
    }
    __syncthreads();

    u64 v[2];
    #pragma unroll
    for (int r = 0; r < 2; r++) {
        int i = i0 + (r << 5);
        v[r] = (i < NQ) ? __ldcg(&g_keys[b * NQ + i]) : 0ULL;  // pads sort below real keys
    }

    // k=2..16
    phase_shfl<2, 1>(v, lane, warp);
    phase_shfl<4, 2>(v, lane, warp); phase_shfl<4, 1>(v, lane, warp);
    phase_shfl<8, 4>(v, lane, warp); phase_shfl<8, 2>(v, lane, warp); phase_shfl<8, 1>(v, lane, warp);
    phase_shfl<16, 8>(v, lane, warp); phase_shfl<16, 4>(v, lane, warp);
    phase_shfl<16, 2>(v, lane, warp); phase_shfl<16, 1>(v, lane, warp);
    // k=32
    phases_shfl_16_1<32>(v, lane, warp);
    // k=64
    phase_reg32<64>(v, warp);
    phases_shfl_16_1<64>(v, lane, warp);
    // k=128
    phase_smem<128, 64, 0>(v, sm, i0);
    phase_reg32<128>(v, warp);
    phases_shfl_16_1<128>(v, lane, warp);
    // k=256
    phase_smem<256, 128, 1>(v, sm, i0);
    phase_smem<256,  64, 0>(v, sm, i0);
    phase_reg32<256>(v, warp);
    phases_shfl_16_1<256>(v, lane, warp);
    // k=512
    phase_smem<512, 256, 1>(v, sm, i0);
    phase_smem<512, 128, 0>(v, sm, i0);
    phase_smem<512,  64, 1>(v, sm, i0);
    phase_reg32<512>(v, warp);
    phases_shfl_16_1<512>(v, lane, warp);
    // k=1024
    phase_smem<1024, 512, 0>(v, sm, i0);
    phase_smem<1024, 256, 1>(v, sm, i0);
    phase_smem<1024, 128, 0>(v, sm, i0);
    phase_smem<1024,  64, 1>(v, sm, i0);
    phase_reg32<1024>(v, warp);
    phases_shfl_16_1<1024>(v, lane, warp);

    // Epilogue straight from registers (elements 0..299 live in warps 0..4)
    float img_h = tsizes[b * 2 + 0];
    float img_w = tsizes[b * 2 + 1];
    const float4* bx4 = reinterpret_cast<const float4*>(boxes) + (size_t)b * NQ;

    #pragma unroll
    for (int r = 0; r < 2; r++) {
        int i = i0 + (r << 5);
        if (i >= TOPK) continue;
        u64 key = v[r];
        float masked = ikey((u32)(key >> 17));
        int label = (int)(key & 127ULL);
        int qi = 1023 - (int)((key >> 7) & 1023ULL);
        bool valid = masked > THRESH;

        float4 bx = bx4[qi];
        float x0 = (bx.x - 0.5f * bx.z) * img_w;
        float y0 = (bx.y - 0.5f * bx.w) * img_h;
        float x1 = (bx.x + 0.5f * bx.z) * img_w;
        float y1 = (bx.y + 0.5f * bx.w) * img_h;

        int o = b * TOPK + i;
        out[o] = valid ? masked : 0.0f;
        out[BATCH * TOPK + o] = valid ? (float)label : -1.0f;
        float* ob = out + 2 * BATCH * TOPK + (size_t)o * 4;
        ob[0] = valid ? x0 : 0.0f;
        ob[1] = valid ? y0 : 0.0f;
        ob[2] = valid ? x1 : 0.0f;
        ob[3] = valid ? y1 : 0.0f;
    }

    if (t == 0) g_done[b] = 0;     // reset for next graph replay
}

// ---------------------------------------------------------------------------
// Fused single-wave kernel:
//   blocks 0..255            : sorter for batch b = bid (spin on doorbell)
//   blocks 256..591 (336)    : persistent producer, tiles j, j+336, ...
// Strided tile order => batches complete in increasing-b order => sorts
// overlap production. >=444 blocks resident (launch_bounds 512,3) > 256
// waiting sorters => producers always schedulable => deadlock-free.
// ---------------------------------------------------------------------------
__global__ void __launch_bounds__(512, 3) k_fused(const float* __restrict__ logits,
                                                  const float* __restrict__ boxes,
                                                  const float* __restrict__ tsizes,
                                                  float* __restrict__ out) {
    __shared__ __align__(16) char smraw[RPB * PAD * 16];   // 43008 B
    int bid = blockIdx.x;

    if (bid < NSORT) {
        do_topk(bid, reinterpret_cast<u64(*)[1024]>(smraw), boxes, tsizes, out);
    } else {
        int j = bid - NSORT;
        float4* sm = reinterpret_cast<float4*>(smraw);
        #pragma unroll 1
        for (int m = j; m < NTILES; m += NPRODB)
            do_tile(m, sm, logits);
    }
}

extern "C" void kernel_launch(void* const* d_in, const int* in_sizes, int n_in,
                              void* d_out, int out_size) {
    const float* pred_logits  = (const float*)d_in[0];
    const float* pred_boxes   = (const float*)d_in[1];
    const float* target_sizes = (const float*)d_in[2];
    float* out = (float*)d_out;

    k_fused<<<GRID, 512>>>(pred_logits, pred_boxes, target_sizes, out);
}

// round 10
// speedup vs baseline: 1.6245x; 1.6245x over previous
#include <cuda_runtime.h>
#include <cuda_bf16.h>
#include <float.h>

#define BATCH 256
#define NQ 1000
#define NC 80
#define TOPK 300
#define THRESH 0.05f

#define RPB 64
#define PAD 21

typedef unsigned long long u64;
typedef unsigned int u32;

__device__ u64 g_keys[BATCH * NQ];

// Order-preserving bijection float -> uint32 (monotone increasing)
__device__ __forceinline__ u32 fkey(float f) {
    u32 u = __float_as_uint(f);
    int  fl = ((int)u) >> 31;
    return u ^ ((u32)fl | 0x80000000u);
}
__device__ __forceinline__ float ikey(u32 k) {
    u32 u = (k & 0x80000000u) ? (k ^ 0x80000000u) : ~k;
    return __uint_as_float(u);
}

// ---------------------------------------------------------------------------
// Kernel 1 (proven R4/R5 config, ~14us, near DRAM roofline): 256 threads
// stage 64 rows (21.5KB, rows padded to 21 float4, coalesced MLP=5), then
// 4 threads/row scan 5 float4 (ascending class order = jax argmax tie-break),
// 2-stage shfl pair reduce. key = [fkey(masked):32 | (1023-qi):10 | label:7]
// ---------------------------------------------------------------------------
__global__ void __launch_bounds__(256) k_maxarg(const float* __restrict__ logits) {
    __shared__ float4 sm[RPB * PAD];
    const float4* in = reinterpret_cast<const float4*>(logits) + (size_t)blockIdx.x * (RPB * 20);
    int t = threadIdx.x;

    #pragma unroll
    for (int u = 0; u < 5; u++) {
        int g = u * 256 + t;
        int row = g / 20;
        int col = g - row * 20;
        sm[row * PAD + col] = in[g];
    }
    __syncthreads();

    int r = t >> 2, q = t & 3;
    const float4* rp = &sm[r * PAD + q * 5];

    float v = -FLT_MAX; int c = 0;
    #pragma unroll
    for (int k = 0; k < 5; k++) {
        float4 x = rp[k];
        int base = q * 20 + k * 4;
        if (x.x > v) { v = x.x; c = base;     }
        if (x.y > v) { v = x.y; c = base + 1; }
        if (x.z > v) { v = x.z; c = base + 2; }
        if (x.w > v) { v = x.w; c = base + 3; }
    }
    #pragma unroll
    for (int off = 1; off <= 2; off <<= 1) {
        float v2 = __shfl_xor_sync(0xffffffffu, v, off);
        int   c2 = __shfl_xor_sync(0xffffffffu, c, off);
        if (v2 > v || (v2 == v && c2 < c)) { v = v2; c = c2; }
    }
    if (q == 0) {
        float s = 1.0f / (1.0f + expf(-v));
        float masked = (s > THRESH) ? s : -1.0f;
        int gq = blockIdx.x * RPB + r;
        int qi = gq % NQ;
        g_keys[gq] = ((u64)fkey(masked) << 17)
                   | ((u64)(1023 - qi) << 7)
                   | (u32)c;
    }
}

// ---------------------------------------------------------------------------
// Kernel 2: proven unrolled bitonic (512 thr, 2 keys/thread, 40 shfl phases,
// 5 register phases, 10 smem phases w/ 1 barrier each) + NEW: box prefetch.
// Boxes for the whole batch are LDG'd into registers BEFORE the sort (latency
// hidden under ~900 sort instructions), STS'd to smem near the end, and the
// epilogue gathers via LDS instead of a dependent random LDG.
// ---------------------------------------------------------------------------
__device__ __forceinline__ u64 shfl_xor_u64(u64 v, int m) {
    u32 lo = __shfl_xor_sync(0xffffffffu, (u32)v, m);
    u32 hi = __shfl_xor_sync(0xffffffffu, (u32)(v >> 32), m);
    return ((u64)hi << 32) | lo;
}

template<int K, int J>
__device__ __forceinline__ void phase_shfl(u64 v[2], int lane, int warp) {
    #pragma unroll
    for (int r = 0; r < 2; r++) {
        int i = (warp << 6) | (r << 5) | lane;
        u64 o = shfl_xor_u64(v[r], J);
        bool keep_hi = ((i & K) == 0) != ((lane & J) != 0);
        bool ogt = o > v[r];
        v[r] = (keep_hi == ogt) ? o : v[r];
    }
}

template<int K>
__device__ __forceinline__ void phase_reg32(u64 v[2], int warp) {
    bool desc = ((warp << 6) & K) == 0;
    u64 a = v[0], b = v[1];
    bool agt = a > b;
    u64 mx = agt ? a : b;
    u64 mn = agt ? b : a;
    v[0] = desc ? mx : mn;
    v[1] = desc ? mn : mx;
}

template<int K, int J, int BUF>
__device__ __forceinline__ void phase_smem(u64 v[2], u64 (*sm)[1024], int i0) {
    sm[BUF][i0]      = v[0];
    sm[BUF][i0 + 32] = v[1];
    __syncthreads();
    #pragma unroll
    for (int r = 0; r < 2; r++) {
        int i = i0 + (r << 5);
        u64 o = sm[BUF][i ^ J];
        bool keep_hi = ((i & K) == 0) != ((i & J) != 0);
        bool ogt = o > v[r];
        v[r] = (keep_hi == ogt) ? o : v[r];
    }
}

template<int K>
__device__ __forceinline__ void phases_shfl_16_1(u64 v[2], int lane, int warp) {
    phase_shfl<K, 16>(v, lane, warp);
    phase_shfl<K,  8>(v, lane, warp);
    phase_shfl<K,  4>(v, lane, warp);
    phase_shfl<K,  2>(v, lane, warp);
    phase_shfl<K,  1>(v, lane, warp);
}

__global__ void __launch_bounds__(512) k_topk(const float* __restrict__ boxes,
                                              const float* __restrict__ tsizes,
                                              float* __restrict__ out) {
    __shared__ u64   sm[2][1024];        // 16KB sort buffer
    __shared__ float4 sbox[1024];        // 16KB box cache (1000 used)
    int b = blockIdx.x;
    int t = threadIdx.x;
    int warp = t >> 5, lane = t & 31;
    int i0 = (warp << 6) | lane;

    // Prefetch this batch's boxes into registers (independent of the sort;
    // the ~900-instruction sort hides the DRAM latency).
    const float4* bx4 = reinterpret_cast<const float4*>(boxes) + (size_t)b * NQ;
    float4 pb0, pb1;
    bool h0 = t < NQ, h1 = t + 512 < NQ;
    if (h0) pb0 = bx4[t];
    if (h1) pb1 = bx4[t + 512];

    u64 v[2];
    #pragma unroll
    for (int r = 0; r < 2; r++) {
        int i = i0 + (r << 5);
        v[r] = (i < NQ) ? g_keys[b * NQ + i] : 0ULL;   // pads sort below real keys
    }

    // k=2..16
    phase_shfl<2, 1>(v, lane, warp);
    phase_shfl<4, 2>(v, lane, warp); phase_shfl<4, 1>(v, lane, warp);
    phase_shfl<8, 4>(v, lane, warp); phase_shfl<8, 2>(v, lane, warp); phase_shfl<8, 1>(v, lane, warp);
    phase_shfl<16, 8>(v, lane, warp); phase_shfl<16, 4>(v, lane, warp);
    phase_shfl<16, 2>(v, lane, warp); phase_shfl<16, 1>(v, lane, warp);
    // k=32
    phases_shfl_16_1<32>(v, lane, warp);
    // k=64
    phase_reg32<64>(v, warp);
    phases_shfl_16_1<64>(v, lane, warp);
    // k=128
    phase_smem<128, 64, 0>(v, sm, i0);
    phase_reg32<128>(v, warp);
    phases_shfl_16_1<128>(v, lane, warp);
    // k=256
    phase_smem<256, 128, 1>(v, sm, i0);
    phase_smem<256,  64, 0>(v, sm, i0);
    phase_reg32<256>(v, warp);
    phases_shfl_16_1<256>(v, lane, warp);
    // k=512
    phase_smem<512, 256, 1>(v, sm, i0);
    phase_smem<512, 128, 0>(v, sm, i0);
    phase_smem<512,  64, 1>(v, sm, i0);
    phase_reg32<512>(v, warp);
    phases_shfl_16_1<512>(v, lane, warp);
    // k=1024
    phase_smem<1024, 512, 0>(v, sm, i0);
    phase_smem<1024, 256, 1>(v, sm, i0);
    phase_smem<1024, 128, 0>(v, sm, i0);
    phase_smem<1024,  64, 1>(v, sm, i0);

    // Park prefetched boxes in smem (loads arrived long ago).
    if (h0) sbox[t] = pb0;
    if (h1) sbox[t + 512] = pb1;

    phase_reg32<1024>(v, warp);
    phases_shfl_16_1<1024>(v, lane, warp);
    __syncthreads();                      // sbox visible to all

    // Epilogue straight from registers (elements 0..299 live in warps 0..4)
    float img_h = tsizes[b * 2 + 0];
    float img_w = tsizes[b * 2 + 1];

    #pragma unroll
    for (int r = 0; r < 2; r++) {
        int i = i0 + (r << 5);
        if (i >= TOPK) continue;
        u64 key = v[r];
        float masked = ikey((u32)(key >> 17));
        int label = (int)(key & 127ULL);
        int qi = 1023 - (int)((key >> 7) & 1023ULL);
        bool valid = masked > THRESH;

        float4 bx = sbox[qi];
        float4 ob;
        ob.x = valid ? (bx.x - 0.5f * bx.z) * img_w : 0.0f;
        ob.y = valid ? (bx.y - 0.5f * bx.w) * img_h : 0.0f;
        ob.z = valid ? (bx.x + 0.5f * bx.z) * img_w : 0.0f;
        ob.w = valid ? (bx.y + 0.5f * bx.w) * img_h : 0.0f;

        int o = b * TOPK + i;
        out[o] = valid ? masked : 0.0f;
        out[BATCH * TOPK + o] = valid ? (float)label : -1.0f;
        reinterpret_cast<float4*>(out + 2 * BATCH * TOPK)[o] = ob;
    }
}

extern "C" void kernel_launch(void* const* d_in, const int* in_sizes, int n_in,
                              void* d_out, int out_size) {
    const float* pred_logits  = (const float*)d_in[0];
    const float* pred_boxes   = (const float*)d_in[1];
    const float* target_sizes = (const float*)d_in[2];
    float* out = (float*)d_out;

    k_maxarg<<<BATCH * NQ / RPB, 256>>>(pred_logits);   // 4000 blocks, 64 rows
    k_topk<<<BATCH, 512>>>(pred_boxes, target_sizes, out);
}